// round 2
// baseline (speedup 1.0000x reference)
#include <cuda_runtime.h>
#include <cstdint>

#define M_NODES 100000
#define K_DIM   256
#define N_DIM   128
#define N_EDGES 1600000

// Intermediate h = x @ W, kept in a static device buffer (alloc-free rule).
// 100000 * 128 floats = 51.2 MB -> L2-resident during the scatter phase.
__device__ float g_h[(size_t)M_NODES * N_DIM];

// ---------------------------------------------------------------------------
// GEMM: h[M,128] = x[M,256] @ W[256,128], fp32.
// Tiling: BM=64, BN=128 (full N), BK=32. 256 threads, each computes 4x8.
// ---------------------------------------------------------------------------
#define BM 64
#define BK 32
#define BN 128
#define XS_STRIDE (BM + 4)   // pad to 68 floats: avoids store conflicts, keeps 16B alignment

__global__ __launch_bounds__(256) void gemm_kernel(const float* __restrict__ x,
                                                   const float* __restrict__ W) {
    __shared__ float xs[BK][XS_STRIDE];  // k-major x tile
    __shared__ float ws[BK][BN];

    const int tid = threadIdx.x;
    const int tx = tid & 15;        // 0..15 -> col group (8 cols each)
    const int ty = tid >> 4;        // 0..15 -> row group (4 rows each)
    const int row0 = blockIdx.x * BM;

    float acc[4][8];
#pragma unroll
    for (int i = 0; i < 4; i++)
#pragma unroll
        for (int j = 0; j < 8; j++) acc[i][j] = 0.0f;

    for (int k0 = 0; k0 < K_DIM; k0 += BK) {
        // Load x tile (64 rows x 32 k) transposed into xs[k][m].
#pragma unroll
        for (int i = 0; i < 2; i++) {
            int linear = tid + i * 256;      // 0..511
            int m = linear >> 3;             // 0..63
            int q = linear & 7;              // float4 index along k
            int grow = row0 + m;
            float4 v = make_float4(0.f, 0.f, 0.f, 0.f);
            if (grow < M_NODES)
                v = *(const float4*)&x[(size_t)grow * K_DIM + k0 + q * 4];
            xs[q * 4 + 0][m] = v.x;
            xs[q * 4 + 1][m] = v.y;
            xs[q * 4 + 2][m] = v.z;
            xs[q * 4 + 3][m] = v.w;
        }
        // Load W tile (32 k x 128 n).
#pragma unroll
        for (int i = 0; i < 4; i++) {
            int linear = tid + i * 256;      // 0..1023
            int n4 = linear & 31;            // float4 col
            int k = linear >> 5;             // 0..31
            *(float4*)&ws[k][n4 * 4] =
                *(const float4*)&W[(size_t)(k0 + k) * N_DIM + n4 * 4];
        }
        __syncthreads();

#pragma unroll
        for (int kk = 0; kk < BK; kk++) {
            float4 a  = *(const float4*)&xs[kk][ty * 4];
            float4 b0 = *(const float4*)&ws[kk][tx * 8];
            float4 b1 = *(const float4*)&ws[kk][tx * 8 + 4];
            float av[4] = {a.x, a.y, a.z, a.w};
            float bv[8] = {b0.x, b0.y, b0.z, b0.w, b1.x, b1.y, b1.z, b1.w};
#pragma unroll
            for (int i = 0; i < 4; i++)
#pragma unroll
                for (int j = 0; j < 8; j++)
                    acc[i][j] = fmaf(av[i], bv[j], acc[i][j]);
        }
        __syncthreads();
    }

#pragma unroll
    for (int i = 0; i < 4; i++) {
        int grow = row0 + ty * 4 + i;
        if (grow < M_NODES) {
            *(float4*)&g_h[(size_t)grow * N_DIM + tx * 8] =
                make_float4(acc[i][0], acc[i][1], acc[i][2], acc[i][3]);
            *(float4*)&g_h[(size_t)grow * N_DIM + tx * 8 + 4] =
                make_float4(acc[i][4], acc[i][5], acc[i][6], acc[i][7]);
        }
    }
}

// ---------------------------------------------------------------------------
// Scatter: one warp per edge. Lane i handles 4 contiguous floats of the
// 128-wide row; uses vectorized red.global.add.v4.f32 (sm_90+).
// ---------------------------------------------------------------------------
__device__ __forceinline__ void red_add_v4(float* addr, float4 v) {
    asm volatile("red.global.add.v4.f32 [%0], {%1, %2, %3, %4};"
                 :: "l"(addr), "f"(v.x), "f"(v.y), "f"(v.z), "f"(v.w)
                 : "memory");
}

__global__ __launch_bounds__(256) void scatter_kernel(const int* __restrict__ rows,
                                                      const int* __restrict__ cols,
                                                      const float* __restrict__ vals,
                                                      float* __restrict__ out) {
    int warp = (blockIdx.x * blockDim.x + threadIdx.x) >> 5;
    int lane = threadIdx.x & 31;
    if (warp >= N_EDGES) return;

    int   r = rows[warp];
    int   c = cols[warp];
    float v = vals[warp];

    float4 hv = *(const float4*)(g_h + (size_t)c * N_DIM + lane * 4);
    float4 m = make_float4(v * hv.x, v * hv.y, v * hv.z, v * hv.w);
    red_add_v4(out + (size_t)r * N_DIM + lane * 4, m);
}

// ---------------------------------------------------------------------------
// ReLU in place over out.
// ---------------------------------------------------------------------------
__global__ __launch_bounds__(256) void relu_kernel(float* __restrict__ out, int n4) {
    int i = blockIdx.x * blockDim.x + threadIdx.x;
    if (i < n4) {
        float4 v = ((float4*)out)[i];
        v.x = fmaxf(v.x, 0.f);
        v.y = fmaxf(v.y, 0.f);
        v.z = fmaxf(v.z, 0.f);
        v.w = fmaxf(v.w, 0.f);
        ((float4*)out)[i] = v;
    }
}

extern "C" void kernel_launch(void* const* d_in, const int* in_sizes, int n_in,
                              void* d_out, int out_size) {
    const float* x    = (const float*)d_in[0];
    const float* W    = (const float*)d_in[1];
    const int*   rows = (const int*)d_in[2];
    const int*   cols = (const int*)d_in[3];
    const float* vals = (const float*)d_in[4];
    float* out = (float*)d_out;

    // Zero the accumulation buffer (out is poisoned to 0xAA).
    cudaMemsetAsync(out, 0, (size_t)out_size * sizeof(float), 0);

    // 1) h = x @ W
    gemm_kernel<<<(M_NODES + BM - 1) / BM, 256>>>(x, W);

    // 2) out[r] += v * h[c]  (one warp per edge, 8 edges per block)
    scatter_kernel<<<(N_EDGES + 7) / 8, 256>>>(rows, cols, vals, out);

    // 3) relu in place
    int n4 = M_NODES * N_DIM / 4;
    relu_kernel<<<(n4 + 255) / 256, 256>>>(out, n4);
}

// round 7
// speedup vs baseline: 1.4825x; 1.4825x over previous
#include <cuda_runtime.h>
#include <cuda_bf16.h>
#include <cstdint>

#define M_NODES 100000
#define K_DIM   256
#define N_DIM   128
#define N_EDGES 1600000

// Intermediate h = x @ W (fp32), L2-resident during scatter.
__device__ float g_h[(size_t)M_NODES * N_DIM];
// Pre-split, pre-transposed weights: [N=128][K=256] bf16, K-major.
__device__ __nv_bfloat16 g_Wt_hi[(size_t)N_DIM * K_DIM];
__device__ __nv_bfloat16 g_Wt_lo[(size_t)N_DIM * K_DIM];

__device__ __forceinline__ uint32_t smem_u32(const void* p) {
    uint32_t a;
    asm("{ .reg .u64 t; cvta.to.shared.u64 t, %1; cvt.u32.u64 %0, t; }" : "=r"(a) : "l"(p));
    return a;
}
#define SW128(off) ((off) ^ (((off) >> 3) & 0x70))

// ---------------------------------------------------------------------------
// W pre-split: g_Wt_{hi,lo}[n][k] = split(W[k][n])
// ---------------------------------------------------------------------------
__global__ void wconv_kernel(const float* __restrict__ W) {
    int idx = blockIdx.x * blockDim.x + threadIdx.x;   // 0..32767
    int n = idx >> 8, k = idx & 255;
    float w = W[(size_t)k * N_DIM + n];
    __nv_bfloat16 hi = __float2bfloat16_rn(w);
    __nv_bfloat16 lo = __float2bfloat16_rn(w - __bfloat162float(hi));
    g_Wt_hi[idx] = hi;
    g_Wt_lo[idx] = lo;
}

// ---------------------------------------------------------------------------
// mma.sync bf16 GEMM (baseline-ISA; tcgen05 is rejected by the bench's
// compute_103 PTX target). CTA tile M128 x N128, K chunk 64, 256 threads.
// Warp tile m64 x n32. 3-term bf16 split for fp32-grade accuracy.
// SMEM: A_hi/A_lo [128m x 64k] bf16 SW128 + B_hi/B_lo [128n x 64k] = 64KB.
// ---------------------------------------------------------------------------
#define KC 64
#define SA_HI 0
#define SA_LO 16384
#define SB_HI 32768
#define SB_LO 49152
#define SMEM_TOTAL 65536

__device__ __forceinline__ void ldsm_x4(uint32_t& r0, uint32_t& r1,
                                        uint32_t& r2, uint32_t& r3, uint32_t addr) {
    asm volatile("ldmatrix.sync.aligned.m8n8.x4.shared.b16 {%0,%1,%2,%3}, [%4];"
                 : "=r"(r0), "=r"(r1), "=r"(r2), "=r"(r3) : "r"(addr));
}
__device__ __forceinline__ void mma_bf16(float* c, const uint32_t* a, const uint32_t* b) {
    asm volatile("mma.sync.aligned.m16n8k16.row.col.f32.bf16.bf16.f32 "
                 "{%0,%1,%2,%3}, {%4,%5,%6,%7}, {%8,%9}, {%0,%1,%2,%3};"
                 : "+f"(c[0]), "+f"(c[1]), "+f"(c[2]), "+f"(c[3])
                 : "r"(a[0]), "r"(a[1]), "r"(a[2]), "r"(a[3]), "r"(b[0]), "r"(b[1]));
}

__global__ __launch_bounds__(256, 2) void gemm_mma_kernel(const float* __restrict__ x) {
    extern __shared__ char smem[];
    const uint32_t sb = smem_u32(smem);
    const int tid  = threadIdx.x;
    const int wid  = tid >> 5;
    const int lane = tid & 31;
    const int row0 = blockIdx.x * 128;

    const int wm = wid & 1;        // 0..1 -> m offset 0/64
    const int wn = wid >> 1;       // 0..3 -> n offset 0/32/64/96

    // Load-phase mapping: thread -> (A row r, k-half h)
    const int lr = tid >> 1;              // 0..127
    const int lh = tid & 1;               // 0..1 (32 k each)
    const int grow_ld = row0 + lr;
    const bool rok = (grow_ld < M_NODES);
    const float4* __restrict__ xrow = (const float4*)(x + (size_t)(rok ? grow_ld : 0) * K_DIM);
    const uint4* __restrict__ wt_hi = (const uint4*)g_Wt_hi;
    const uint4* __restrict__ wt_lo = (const uint4*)g_Wt_lo;

    // ldmatrix per-lane address components
    const int a_row = wm * 64 + (lane & 15);
    const int a_kbl = (lane & 16);                         // 0 or 16 bytes
    const int b_row = wn * 32 + (lane & 7) + ((lane & 16) ? 8 : 0);
    const int b_kbl = (lane & 8) ? 16 : 0;

    float acc[4][4][4];
#pragma unroll
    for (int mi = 0; mi < 4; mi++)
#pragma unroll
        for (int ni = 0; ni < 4; ni++)
#pragma unroll
            for (int i = 0; i < 4; i++) acc[mi][ni][i] = 0.f;

    for (int c = 0; c < K_DIM / KC; c++) {
        const int k0 = c * KC;

        // ---- A: load 32 f32, split to bf16 hi/lo, store swizzled ----
        {
            const float4* xr = xrow + ((k0 + lh * 32) >> 2);
            float4 fr[8];
#pragma unroll
            for (int j = 0; j < 8; j++)
                fr[j] = rok ? xr[j] : make_float4(0.f, 0.f, 0.f, 0.f);
            const float* f = (const float*)fr;
#pragma unroll
            for (int j = 0; j < 4; j++) {          // j -> 8 elems -> one uint4
                uint32_t ph[4], pl[4];
#pragma unroll
                for (int i = 0; i < 4; i++) {
                    float f0 = f[j * 8 + 2 * i], f1 = f[j * 8 + 2 * i + 1];
                    __nv_bfloat16 h0 = __float2bfloat16_rn(f0);
                    __nv_bfloat16 h1 = __float2bfloat16_rn(f1);
                    __nv_bfloat162 hp = __halves2bfloat162(h0, h1);
                    __nv_bfloat162 lp = __halves2bfloat162(
                        __float2bfloat16_rn(f0 - __bfloat162float(h0)),
                        __float2bfloat16_rn(f1 - __bfloat162float(h1)));
                    ph[i] = *(uint32_t*)&hp;
                    pl[i] = *(uint32_t*)&lp;
                }
                uint32_t off = SW128((uint32_t)(lr * 128 + lh * 64 + j * 16));
                *(uint4*)(smem + SA_HI + off) = make_uint4(ph[0], ph[1], ph[2], ph[3]);
                *(uint4*)(smem + SA_LO + off) = make_uint4(pl[0], pl[1], pl[2], pl[3]);
            }
        }
        // ---- B: copy pre-split bf16 tiles (n-row lr, k-half lh) ----
        {
            const int gbase = (lr * K_DIM + k0 + lh * 32) >> 3;   // uint4 index
#pragma unroll
            for (int j = 0; j < 4; j++) {
                uint32_t off = SW128((uint32_t)(lr * 128 + lh * 64 + j * 16));
                *(uint4*)(smem + SB_HI + off) = wt_hi[gbase + j];
                *(uint4*)(smem + SB_LO + off) = wt_lo[gbase + j];
            }
        }
        __syncthreads();

        // ---- Compute: 4 k16 steps ----
#pragma unroll
        for (int ks = 0; ks < 4; ks++) {
            const int kbase = ks * 32;
            uint32_t bh[8], bl[8];
#pragma unroll
            for (int g = 0; g < 2; g++) {
                uint32_t off = SW128((uint32_t)((b_row + g * 16) * 128 + kbase + b_kbl));
                ldsm_x4(bh[g * 4 + 0], bh[g * 4 + 1], bh[g * 4 + 2], bh[g * 4 + 3],
                        sb + SB_HI + off);
                ldsm_x4(bl[g * 4 + 0], bl[g * 4 + 1], bl[g * 4 + 2], bl[g * 4 + 3],
                        sb + SB_LO + off);
            }
#pragma unroll
            for (int mi = 0; mi < 4; mi++) {
                uint32_t ah[4], al[4];
                uint32_t off = SW128((uint32_t)((a_row + mi * 16) * 128 + kbase + a_kbl));
                ldsm_x4(ah[0], ah[1], ah[2], ah[3], sb + SA_HI + off);
                ldsm_x4(al[0], al[1], al[2], al[3], sb + SA_LO + off);
#pragma unroll
                for (int ni = 0; ni < 4; ni++) {
                    mma_bf16(acc[mi][ni], ah, &bh[ni * 2]);
                    mma_bf16(acc[mi][ni], ah, &bl[ni * 2]);
                    mma_bf16(acc[mi][ni], al, &bh[ni * 2]);
                }
            }
        }
        __syncthreads();
    }

    // ---- Epilogue: c-frag (row = T/4 (+8), col = 2*(T%4)+{0,1}) ----
    const int er = lane >> 2;
    const int ec = (lane & 3) * 2;
#pragma unroll
    for (int mi = 0; mi < 4; mi++) {
        int grow = row0 + wm * 64 + mi * 16 + er;
#pragma unroll
        for (int ni = 0; ni < 4; ni++) {
            int col = wn * 32 + ni * 8 + ec;
            if (grow < M_NODES)
                *(float2*)(g_h + (size_t)grow * N_DIM + col) =
                    make_float2(acc[mi][ni][0], acc[mi][ni][1]);
            if (grow + 8 < M_NODES)
                *(float2*)(g_h + (size_t)(grow + 8) * N_DIM + col) =
                    make_float2(acc[mi][ni][2], acc[mi][ni][3]);
        }
    }
}

// ---------------------------------------------------------------------------
// Scatter: one warp per edge, red.global.add.v4.f32 per lane.
// ---------------------------------------------------------------------------
__device__ __forceinline__ void red_add_v4(float* addr, float4 v) {
    asm volatile("red.global.add.v4.f32 [%0], {%1, %2, %3, %4};"
                 :: "l"(addr), "f"(v.x), "f"(v.y), "f"(v.z), "f"(v.w)
                 : "memory");
}

__global__ __launch_bounds__(256) void scatter_kernel(const int* __restrict__ rows,
                                                      const int* __restrict__ cols,
                                                      const float* __restrict__ vals,
                                                      float* __restrict__ out) {
    int warp = (blockIdx.x * blockDim.x + threadIdx.x) >> 5;
    int lane = threadIdx.x & 31;
    if (warp >= N_EDGES) return;

    int   r = rows[warp];
    int   c = cols[warp];
    float v = vals[warp];

    float4 hv = *(const float4*)(g_h + (size_t)c * N_DIM + lane * 4);
    float4 m = make_float4(v * hv.x, v * hv.y, v * hv.z, v * hv.w);
    red_add_v4(out + (size_t)r * N_DIM + lane * 4, m);
}

__global__ __launch_bounds__(256) void relu_kernel(float* __restrict__ out, int n4) {
    int i = blockIdx.x * blockDim.x + threadIdx.x;
    if (i < n4) {
        float4 v = ((float4*)out)[i];
        v.x = fmaxf(v.x, 0.f);
        v.y = fmaxf(v.y, 0.f);
        v.z = fmaxf(v.z, 0.f);
        v.w = fmaxf(v.w, 0.f);
        ((float4*)out)[i] = v;
    }
}

extern "C" void kernel_launch(void* const* d_in, const int* in_sizes, int n_in,
                              void* d_out, int out_size) {
    const float* x    = (const float*)d_in[0];
    const float* W    = (const float*)d_in[1];
    const int*   rows = (const int*)d_in[2];
    const int*   cols = (const int*)d_in[3];
    const float* vals = (const float*)d_in[4];
    float* out = (float*)d_out;

    cudaFuncSetAttribute(gemm_mma_kernel,
                         cudaFuncAttributeMaxDynamicSharedMemorySize, SMEM_TOTAL);

    cudaMemsetAsync(out, 0, (size_t)out_size * sizeof(float), 0);

    // 0) split + transpose W
    wconv_kernel<<<(N_DIM * K_DIM) / 256, 256>>>(W);

    // 1) h = x @ W  (mma.sync bf16, 3-term split)
    gemm_mma_kernel<<<(M_NODES + 127) / 128, 256, SMEM_TOTAL>>>(x);

    // 2) out[r] += v * h[c]
    scatter_kernel<<<(N_EDGES + 7) / 8, 256>>>(rows, cols, vals, out);

    // 3) relu
    int n4 = M_NODES * N_DIM / 4;
    relu_kernel<<<(n4 + 255) / 256, 256>>>(out, n4);
}

// round 10
// speedup vs baseline: 1.6340x; 1.1023x over previous
#include <cuda_runtime.h>
#include <cuda_bf16.h>
#include <cstdint>

#define M_NODES 100000
#define K_DIM   256
#define N_DIM   128
#define N_EDGES 1600000

#define SCAN_N   100352            // M_NODES padded to 392*256
#define SCAN_BLK 392

// Intermediate h = x @ W (fp32), L2-resident during gather.
__device__ float g_h[(size_t)M_NODES * N_DIM];
// Pre-split, pre-transposed weights: [N=128][K=256] bf16, K-major.
__device__ __nv_bfloat16 g_Wt_hi[(size_t)N_DIM * K_DIM];
__device__ __nv_bfloat16 g_Wt_lo[(size_t)N_DIM * K_DIM];
// CSR scratch
__device__ int      g_count[SCAN_N];
__device__ int      g_off[SCAN_N];
__device__ int      g_cursor[SCAN_N];
__device__ int      g_bsum[SCAN_BLK];
__device__ int      g_bbase[SCAN_BLK];
__device__ uint64_t g_csr[N_EDGES];   // packed {val_bits:32 | col:32}

__device__ __forceinline__ uint32_t smem_u32(const void* p) {
    uint32_t a;
    asm("{ .reg .u64 t; cvta.to.shared.u64 t, %1; cvt.u32.u64 %0, t; }" : "=r"(a) : "l"(p));
    return a;
}
#define SW128(off) ((off) ^ (((off) >> 3) & 0x70))

// ---------------------------------------------------------------------------
// W pre-split: g_Wt_{hi,lo}[n][k] = split(W[k][n])
// ---------------------------------------------------------------------------
__global__ void wconv_kernel(const float* __restrict__ W) {
    int idx = blockIdx.x * blockDim.x + threadIdx.x;   // 0..32767
    int n = idx >> 8, k = idx & 255;
    float w = W[(size_t)k * N_DIM + n];
    __nv_bfloat16 hi = __float2bfloat16_rn(w);
    __nv_bfloat16 lo = __float2bfloat16_rn(w - __bfloat162float(hi));
    g_Wt_hi[idx] = hi;
    g_Wt_lo[idx] = lo;
}

// ---------------------------------------------------------------------------
// mma.sync bf16 GEMM, CTA tile M128xN128, K chunk 64, 3-term split.
// ---------------------------------------------------------------------------
#define KC 64
#define SA_HI 0
#define SA_LO 16384
#define SB_HI 32768
#define SB_LO 49152
#define SMEM_TOTAL 65536

__device__ __forceinline__ void ldsm_x4(uint32_t& r0, uint32_t& r1,
                                        uint32_t& r2, uint32_t& r3, uint32_t addr) {
    asm volatile("ldmatrix.sync.aligned.m8n8.x4.shared.b16 {%0,%1,%2,%3}, [%4];"
                 : "=r"(r0), "=r"(r1), "=r"(r2), "=r"(r3) : "r"(addr));
}
__device__ __forceinline__ void mma_bf16(float* c, const uint32_t* a, const uint32_t* b) {
    asm volatile("mma.sync.aligned.m16n8k16.row.col.f32.bf16.bf16.f32 "
                 "{%0,%1,%2,%3}, {%4,%5,%6,%7}, {%8,%9}, {%0,%1,%2,%3};"
                 : "+f"(c[0]), "+f"(c[1]), "+f"(c[2]), "+f"(c[3])
                 : "r"(a[0]), "r"(a[1]), "r"(a[2]), "r"(a[3]), "r"(b[0]), "r"(b[1]));
}

__global__ __launch_bounds__(256, 2) void gemm_mma_kernel(const float* __restrict__ x) {
    extern __shared__ char smem[];
    const uint32_t sb = smem_u32(smem);
    const int tid  = threadIdx.x;
    const int wid  = tid >> 5;
    const int lane = tid & 31;
    const int row0 = blockIdx.x * 128;

    const int wm = wid & 1;
    const int wn = wid >> 1;

    const int lr = tid >> 1;
    const int lh = tid & 1;
    const int grow_ld = row0 + lr;
    const bool rok = (grow_ld < M_NODES);
    const float4* __restrict__ xrow = (const float4*)(x + (size_t)(rok ? grow_ld : 0) * K_DIM);
    const uint4* __restrict__ wt_hi = (const uint4*)g_Wt_hi;
    const uint4* __restrict__ wt_lo = (const uint4*)g_Wt_lo;

    const int a_row = wm * 64 + (lane & 15);
    const int a_kbl = (lane & 16);
    const int b_row = wn * 32 + (lane & 7) + ((lane & 16) ? 8 : 0);
    const int b_kbl = (lane & 8) ? 16 : 0;

    float acc[4][4][4];
#pragma unroll
    for (int mi = 0; mi < 4; mi++)
#pragma unroll
        for (int ni = 0; ni < 4; ni++)
#pragma unroll
            for (int i = 0; i < 4; i++) acc[mi][ni][i] = 0.f;

    for (int c = 0; c < K_DIM / KC; c++) {
        const int k0 = c * KC;
        {
            const float4* xr = xrow + ((k0 + lh * 32) >> 2);
            float4 fr[8];
#pragma unroll
            for (int j = 0; j < 8; j++)
                fr[j] = rok ? xr[j] : make_float4(0.f, 0.f, 0.f, 0.f);
            const float* f = (const float*)fr;
#pragma unroll
            for (int j = 0; j < 4; j++) {
                uint32_t ph[4], pl[4];
#pragma unroll
                for (int i = 0; i < 4; i++) {
                    float f0 = f[j * 8 + 2 * i], f1 = f[j * 8 + 2 * i + 1];
                    __nv_bfloat16 h0 = __float2bfloat16_rn(f0);
                    __nv_bfloat16 h1 = __float2bfloat16_rn(f1);
                    __nv_bfloat162 hp = __halves2bfloat162(h0, h1);
                    __nv_bfloat162 lp = __halves2bfloat162(
                        __float2bfloat16_rn(f0 - __bfloat162float(h0)),
                        __float2bfloat16_rn(f1 - __bfloat162float(h1)));
                    ph[i] = *(uint32_t*)&hp;
                    pl[i] = *(uint32_t*)&lp;
                }
                uint32_t off = SW128((uint32_t)(lr * 128 + lh * 64 + j * 16));
                *(uint4*)(smem + SA_HI + off) = make_uint4(ph[0], ph[1], ph[2], ph[3]);
                *(uint4*)(smem + SA_LO + off) = make_uint4(pl[0], pl[1], pl[2], pl[3]);
            }
        }
        {
            const int gbase = (lr * K_DIM + k0 + lh * 32) >> 3;
#pragma unroll
            for (int j = 0; j < 4; j++) {
                uint32_t off = SW128((uint32_t)(lr * 128 + lh * 64 + j * 16));
                *(uint4*)(smem + SB_HI + off) = wt_hi[gbase + j];
                *(uint4*)(smem + SB_LO + off) = wt_lo[gbase + j];
            }
        }
        __syncthreads();

#pragma unroll
        for (int ks = 0; ks < 4; ks++) {
            const int kbase = ks * 32;
            uint32_t bh[8], bl[8];
#pragma unroll
            for (int g = 0; g < 2; g++) {
                uint32_t off = SW128((uint32_t)((b_row + g * 16) * 128 + kbase + b_kbl));
                ldsm_x4(bh[g * 4 + 0], bh[g * 4 + 1], bh[g * 4 + 2], bh[g * 4 + 3],
                        sb + SB_HI + off);
                ldsm_x4(bl[g * 4 + 0], bl[g * 4 + 1], bl[g * 4 + 2], bl[g * 4 + 3],
                        sb + SB_LO + off);
            }
#pragma unroll
            for (int mi = 0; mi < 4; mi++) {
                uint32_t ah[4], al[4];
                uint32_t off = SW128((uint32_t)((a_row + mi * 16) * 128 + kbase + a_kbl));
                ldsm_x4(ah[0], ah[1], ah[2], ah[3], sb + SA_HI + off);
                ldsm_x4(al[0], al[1], al[2], al[3], sb + SA_LO + off);
#pragma unroll
                for (int ni = 0; ni < 4; ni++) {
                    mma_bf16(acc[mi][ni], ah, &bh[ni * 2]);
                    mma_bf16(acc[mi][ni], ah, &bl[ni * 2]);
                    mma_bf16(acc[mi][ni], al, &bh[ni * 2]);
                }
            }
        }
        __syncthreads();
    }

    const int er = lane >> 2;
    const int ec = (lane & 3) * 2;
#pragma unroll
    for (int mi = 0; mi < 4; mi++) {
        int grow = row0 + wm * 64 + mi * 16 + er;
#pragma unroll
        for (int ni = 0; ni < 4; ni++) {
            int col = wn * 32 + ni * 8 + ec;
            if (grow < M_NODES)
                *(float2*)(g_h + (size_t)grow * N_DIM + col) =
                    make_float2(acc[mi][ni][0], acc[mi][ni][1]);
            if (grow + 8 < M_NODES)
                *(float2*)(g_h + (size_t)(grow + 8) * N_DIM + col) =
                    make_float2(acc[mi][ni][2], acc[mi][ni][3]);
        }
    }
}

// ---------------------------------------------------------------------------
// CSR build: zero -> count -> scan(local, bsums, add) -> fill
// ---------------------------------------------------------------------------
__global__ __launch_bounds__(256) void zero_kernel() {
    int i = blockIdx.x * blockDim.x + threadIdx.x;
    g_count[i] = 0;
}

__global__ __launch_bounds__(256) void count_kernel(const int* __restrict__ rows) {
    int i = blockIdx.x * blockDim.x + threadIdx.x;
    if (i < N_EDGES) atomicAdd(&g_count[rows[i]], 1);
}

__global__ __launch_bounds__(256) void scan_local_kernel() {
    __shared__ int s[256];
    int t = threadIdx.x, b = blockIdx.x;
    int i = b * 256 + t;
    int c = g_count[i];
    s[t] = c;
    __syncthreads();
    int v = c;
#pragma unroll
    for (int d = 1; d < 256; d <<= 1) {
        int add = (t >= d) ? s[t - d] : 0;
        __syncthreads();
        v += add;
        s[t] = v;
        __syncthreads();
    }
    g_off[i] = v - c;                 // exclusive, block-local
    if (t == 255) g_bsum[b] = v;      // block total
}

__global__ __launch_bounds__(512) void scan_bsums_kernel() {
    __shared__ int s[512];
    int t = threadIdx.x;
    int c = (t < SCAN_BLK) ? g_bsum[t] : 0;
    s[t] = c;
    __syncthreads();
    int v = c;
#pragma unroll
    for (int d = 1; d < 512; d <<= 1) {
        int add = (t >= d) ? s[t - d] : 0;
        __syncthreads();
        v += add;
        s[t] = v;
        __syncthreads();
    }
    if (t < SCAN_BLK) g_bbase[t] = v - c;   // exclusive
}

__global__ __launch_bounds__(256) void scan_add_kernel() {
    int i = blockIdx.x * blockDim.x + threadIdx.x;
    int off = g_off[i] + g_bbase[blockIdx.x];
    g_off[i] = off;
    g_cursor[i] = off;
}

__global__ __launch_bounds__(256) void fill_kernel(const int* __restrict__ rows,
                                                   const int* __restrict__ cols,
                                                   const float* __restrict__ vals) {
    int i = blockIdx.x * blockDim.x + threadIdx.x;
    if (i < N_EDGES) {
        int r = rows[i];
        int pos = atomicAdd(&g_cursor[r], 1);
        uint64_t ent = ((uint64_t)__float_as_uint(vals[i]) << 32) | (uint32_t)cols[i];
        g_csr[pos] = ent;
    }
}

// ---------------------------------------------------------------------------
// Gather: one warp per node. Register accumulation, single write, fused relu.
// ---------------------------------------------------------------------------
__global__ __launch_bounds__(256) void gather_kernel(float* __restrict__ out) {
    int warp = (blockIdx.x * blockDim.x + threadIdx.x) >> 5;
    int lane = threadIdx.x & 31;
    if (warp >= M_NODES) return;

    const int start = g_off[warp];
    const int deg   = g_count[warp];

    float4 acc = make_float4(0.f, 0.f, 0.f, 0.f);

    for (int base = 0; base < deg; base += 32) {
        int m = deg - base;
        int lim = (m < 32) ? m : 32;
        uint32_t e_lo = 0, e_hi = 0;
        if (lane < lim) {
            uint64_t ent = g_csr[start + base + lane];
            e_lo = (uint32_t)ent;
            e_hi = (uint32_t)(ent >> 32);
        }
        for (int j = 0; j < lim; j++) {
            int   c = (int)__shfl_sync(0xFFFFFFFFu, e_lo, j);
            float v = __uint_as_float(__shfl_sync(0xFFFFFFFFu, e_hi, j));
            float4 hv = *(const float4*)(g_h + (size_t)c * N_DIM + lane * 4);
            acc.x = fmaf(v, hv.x, acc.x);
            acc.y = fmaf(v, hv.y, acc.y);
            acc.z = fmaf(v, hv.z, acc.z);
            acc.w = fmaf(v, hv.w, acc.w);
        }
    }

    acc.x = fmaxf(acc.x, 0.f);
    acc.y = fmaxf(acc.y, 0.f);
    acc.z = fmaxf(acc.z, 0.f);
    acc.w = fmaxf(acc.w, 0.f);
    *(float4*)(out + (size_t)warp * N_DIM + lane * 4) = acc;
}

extern "C" void kernel_launch(void* const* d_in, const int* in_sizes, int n_in,
                              void* d_out, int out_size) {
    const float* x    = (const float*)d_in[0];
    const float* W    = (const float*)d_in[1];
    const int*   rows = (const int*)d_in[2];
    const int*   cols = (const int*)d_in[3];
    const float* vals = (const float*)d_in[4];
    float* out = (float*)d_out;

    cudaFuncSetAttribute(gemm_mma_kernel,
                         cudaFuncAttributeMaxDynamicSharedMemorySize, SMEM_TOTAL);

    // CSR build (independent of GEMM)
    zero_kernel<<<SCAN_BLK, 256>>>();
    count_kernel<<<(N_EDGES + 255) / 256, 256>>>(rows);
    scan_local_kernel<<<SCAN_BLK, 256>>>();
    scan_bsums_kernel<<<1, 512>>>();
    scan_add_kernel<<<SCAN_BLK, 256>>>();
    fill_kernel<<<(N_EDGES + 255) / 256, 256>>>(rows, cols, vals);

    // Dense projection h = x @ W
    wconv_kernel<<<(N_DIM * K_DIM) / 256, 256>>>(W);
    gemm_mma_kernel<<<(M_NODES + 127) / 128, 256, SMEM_TOTAL>>>(x);

    // Aggregate + relu, single write per row (no memset, no relu pass)
    gather_kernel<<<(M_NODES * 32 + 255) / 256, 256>>>(out);
}

// round 11
// speedup vs baseline: 2.2340x; 1.3672x over previous
#include <cuda_runtime.h>
#include <cuda_bf16.h>
#include <cstdint>

#define M_NODES 100000
#define K_DIM   256
#define N_DIM   128
#define N_EDGES 1600000

#define SCAN_N   100352            // M_NODES padded to 392*256
#define SCAN_BLK 392

// Intermediate h = x @ W (fp32), L2-resident during gather.
__device__ float g_h[(size_t)M_NODES * N_DIM];
// Pre-split, pre-transposed weights: [N=128][K=256] bf16, K-major.
__device__ __nv_bfloat16 g_Wt_hi[(size_t)N_DIM * K_DIM];
__device__ __nv_bfloat16 g_Wt_lo[(size_t)N_DIM * K_DIM];
// CSR scratch
__device__ int      g_count[SCAN_N];
__device__ int      g_off[SCAN_N];
__device__ int      g_cursor[SCAN_N];
__device__ int      g_total;
__device__ uint64_t g_csr[N_EDGES];   // packed {val_bits:32 | col:32}

__device__ __forceinline__ uint32_t smem_u32(const void* p) {
    uint32_t a;
    asm("{ .reg .u64 t; cvta.to.shared.u64 t, %1; cvt.u32.u64 %0, t; }" : "=r"(a) : "l"(p));
    return a;
}
#define SW128(off) ((off) ^ (((off) >> 3) & 0x70))

// ---------------------------------------------------------------------------
// W pre-split: g_Wt_{hi,lo}[n][k] = split(W[k][n])
// ---------------------------------------------------------------------------
__global__ void wconv_kernel(const float* __restrict__ W) {
    int idx = blockIdx.x * blockDim.x + threadIdx.x;   // 0..32767
    int n = idx >> 8, k = idx & 255;
    float w = W[(size_t)k * N_DIM + n];
    __nv_bfloat16 hi = __float2bfloat16_rn(w);
    __nv_bfloat16 lo = __float2bfloat16_rn(w - __bfloat162float(hi));
    g_Wt_hi[idx] = hi;
    g_Wt_lo[idx] = lo;
}

// ---------------------------------------------------------------------------
// mma.sync bf16 GEMM, CTA tile M128xN128, K chunk 64, 3-term split.
// (unchanged from R7 — passing at ~90us; next round's target)
// ---------------------------------------------------------------------------
#define KC 64
#define SA_HI 0
#define SA_LO 16384
#define SB_HI 32768
#define SB_LO 49152
#define SMEM_TOTAL 65536

__device__ __forceinline__ void ldsm_x4(uint32_t& r0, uint32_t& r1,
                                        uint32_t& r2, uint32_t& r3, uint32_t addr) {
    asm volatile("ldmatrix.sync.aligned.m8n8.x4.shared.b16 {%0,%1,%2,%3}, [%4];"
                 : "=r"(r0), "=r"(r1), "=r"(r2), "=r"(r3) : "r"(addr));
}
__device__ __forceinline__ void mma_bf16(float* c, const uint32_t* a, const uint32_t* b) {
    asm volatile("mma.sync.aligned.m16n8k16.row.col.f32.bf16.bf16.f32 "
                 "{%0,%1,%2,%3}, {%4,%5,%6,%7}, {%8,%9}, {%0,%1,%2,%3};"
                 : "+f"(c[0]), "+f"(c[1]), "+f"(c[2]), "+f"(c[3])
                 : "r"(a[0]), "r"(a[1]), "r"(a[2]), "r"(a[3]), "r"(b[0]), "r"(b[1]));
}

__global__ __launch_bounds__(256, 2) void gemm_mma_kernel(const float* __restrict__ x) {
    extern __shared__ char smem[];
    const uint32_t sb = smem_u32(smem);
    const int tid  = threadIdx.x;
    const int wid  = tid >> 5;
    const int lane = tid & 31;
    const int row0 = blockIdx.x * 128;

    const int wm = wid & 1;
    const int wn = wid >> 1;

    const int lr = tid >> 1;
    const int lh = tid & 1;
    const int grow_ld = row0 + lr;
    const bool rok = (grow_ld < M_NODES);
    const float4* __restrict__ xrow = (const float4*)(x + (size_t)(rok ? grow_ld : 0) * K_DIM);
    const uint4* __restrict__ wt_hi = (const uint4*)g_Wt_hi;
    const uint4* __restrict__ wt_lo = (const uint4*)g_Wt_lo;

    const int a_row = wm * 64 + (lane & 15);
    const int a_kbl = (lane & 16);
    const int b_row = wn * 32 + (lane & 7) + ((lane & 16) ? 8 : 0);
    const int b_kbl = (lane & 8) ? 16 : 0;

    float acc[4][4][4];
#pragma unroll
    for (int mi = 0; mi < 4; mi++)
#pragma unroll
        for (int ni = 0; ni < 4; ni++)
#pragma unroll
            for (int i = 0; i < 4; i++) acc[mi][ni][i] = 0.f;

    for (int c = 0; c < K_DIM / KC; c++) {
        const int k0 = c * KC;
        {
            const float4* xr = xrow + ((k0 + lh * 32) >> 2);
            float4 fr[8];
#pragma unroll
            for (int j = 0; j < 8; j++)
                fr[j] = rok ? xr[j] : make_float4(0.f, 0.f, 0.f, 0.f);
            const float* f = (const float*)fr;
#pragma unroll
            for (int j = 0; j < 4; j++) {
                uint32_t ph[4], pl[4];
#pragma unroll
                for (int i = 0; i < 4; i++) {
                    float f0 = f[j * 8 + 2 * i], f1 = f[j * 8 + 2 * i + 1];
                    __nv_bfloat16 h0 = __float2bfloat16_rn(f0);
                    __nv_bfloat16 h1 = __float2bfloat16_rn(f1);
                    __nv_bfloat162 hp = __halves2bfloat162(h0, h1);
                    __nv_bfloat162 lp = __halves2bfloat162(
                        __float2bfloat16_rn(f0 - __bfloat162float(h0)),
                        __float2bfloat16_rn(f1 - __bfloat162float(h1)));
                    ph[i] = *(uint32_t*)&hp;
                    pl[i] = *(uint32_t*)&lp;
                }
                uint32_t off = SW128((uint32_t)(lr * 128 + lh * 64 + j * 16));
                *(uint4*)(smem + SA_HI + off) = make_uint4(ph[0], ph[1], ph[2], ph[3]);
                *(uint4*)(smem + SA_LO + off) = make_uint4(pl[0], pl[1], pl[2], pl[3]);
            }
        }
        {
            const int gbase = (lr * K_DIM + k0 + lh * 32) >> 3;
#pragma unroll
            for (int j = 0; j < 4; j++) {
                uint32_t off = SW128((uint32_t)(lr * 128 + lh * 64 + j * 16));
                *(uint4*)(smem + SB_HI + off) = wt_hi[gbase + j];
                *(uint4*)(smem + SB_LO + off) = wt_lo[gbase + j];
            }
        }
        __syncthreads();

#pragma unroll
        for (int ks = 0; ks < 4; ks++) {
            const int kbase = ks * 32;
            uint32_t bh[8], bl[8];
#pragma unroll
            for (int g = 0; g < 2; g++) {
                uint32_t off = SW128((uint32_t)((b_row + g * 16) * 128 + kbase + b_kbl));
                ldsm_x4(bh[g * 4 + 0], bh[g * 4 + 1], bh[g * 4 + 2], bh[g * 4 + 3],
                        sb + SB_HI + off);
                ldsm_x4(bl[g * 4 + 0], bl[g * 4 + 1], bl[g * 4 + 2], bl[g * 4 + 3],
                        sb + SB_LO + off);
            }
#pragma unroll
            for (int mi = 0; mi < 4; mi++) {
                uint32_t ah[4], al[4];
                uint32_t off = SW128((uint32_t)((a_row + mi * 16) * 128 + kbase + a_kbl));
                ldsm_x4(ah[0], ah[1], ah[2], ah[3], sb + SA_HI + off);
                ldsm_x4(al[0], al[1], al[2], al[3], sb + SA_LO + off);
#pragma unroll
                for (int ni = 0; ni < 4; ni++) {
                    mma_bf16(acc[mi][ni], ah, &bh[ni * 2]);
                    mma_bf16(acc[mi][ni], ah, &bl[ni * 2]);
                    mma_bf16(acc[mi][ni], al, &bh[ni * 2]);
                }
            }
        }
        __syncthreads();
    }

    const int er = lane >> 2;
    const int ec = (lane & 3) * 2;
#pragma unroll
    for (int mi = 0; mi < 4; mi++) {
        int grow = row0 + wm * 64 + mi * 16 + er;
#pragma unroll
        for (int ni = 0; ni < 4; ni++) {
            int col = wn * 32 + ni * 8 + ec;
            if (grow < M_NODES)
                *(float2*)(g_h + (size_t)grow * N_DIM + col) =
                    make_float2(acc[mi][ni][0], acc[mi][ni][1]);
            if (grow + 8 < M_NODES)
                *(float2*)(g_h + (size_t)(grow + 8) * N_DIM + col) =
                    make_float2(acc[mi][ni][2], acc[mi][ni][3]);
        }
    }
}

// ---------------------------------------------------------------------------
// CSR build: zero -> count -> fused scan (atomic block base) -> fill
// ---------------------------------------------------------------------------
__global__ __launch_bounds__(256) void zero_kernel() {
    int i = blockIdx.x * blockDim.x + threadIdx.x;
    g_count[i] = 0;
    if (i == 0) g_total = 0;
}

__global__ __launch_bounds__(256) void count_kernel(const int* __restrict__ rows) {
    int i = blockIdx.x * blockDim.x + threadIdx.x;
    if (i < N_EDGES) atomicAdd(&g_count[rows[i]], 1);
}

// Single-pass: block-local inclusive scan, block base via atomicAdd.
// CSR ranges are disjoint but NOT ordered by node id -- gather only needs
// (off, count) per node, so ordering is irrelevant.
__global__ __launch_bounds__(256) void scan_fused_kernel() {
    __shared__ int s[256];
    __shared__ int base_sh;
    int t = threadIdx.x, b = blockIdx.x;
    int i = b * 256 + t;
    int c = g_count[i];
    s[t] = c;
    __syncthreads();
    int v = c;
#pragma unroll
    for (int d = 1; d < 256; d <<= 1) {
        int add = (t >= d) ? s[t - d] : 0;
        __syncthreads();
        v += add;
        s[t] = v;
        __syncthreads();
    }
    if (t == 255) base_sh = atomicAdd(&g_total, v);
    __syncthreads();
    int off = base_sh + v - c;      // exclusive within block + block base
    g_off[i] = off;
    g_cursor[i] = off;
}

__global__ __launch_bounds__(256) void fill_kernel(const int* __restrict__ rows,
                                                   const int* __restrict__ cols,
                                                   const float* __restrict__ vals) {
    int i = blockIdx.x * blockDim.x + threadIdx.x;
    if (i < N_EDGES) {
        int r = rows[i];
        int pos = atomicAdd(&g_cursor[r], 1);
        uint64_t ent = ((uint64_t)__float_as_uint(vals[i]) << 32) | (uint32_t)cols[i];
        g_csr[pos] = ent;
    }
}

// ---------------------------------------------------------------------------
// Gather: one warp per node. Edge entries staged in smem (LDS broadcast),
// inner loop unrolled x4 for MLP, two accumulators, fused relu.
// ---------------------------------------------------------------------------
__global__ __launch_bounds__(256) void gather_kernel(float* __restrict__ out) {
    __shared__ uint64_t ebuf[8][32];
    const int wib  = threadIdx.x >> 5;           // warp in block
    const int lane = threadIdx.x & 31;
    const int warp = (blockIdx.x * blockDim.x + threadIdx.x) >> 5;
    if (warp >= M_NODES) return;

    const int start = g_off[warp];
    const int deg   = g_count[warp];
    const float4* __restrict__ h4 = (const float4*)g_h;   // 32 float4 per row

    float4 acc0 = make_float4(0.f, 0.f, 0.f, 0.f);
    float4 acc1 = make_float4(0.f, 0.f, 0.f, 0.f);

    for (int base = 0; base < deg; base += 32) {
        int lim = deg - base;
        if (lim > 32) lim = 32;
        __syncwarp();
        if (lane < lim) ebuf[wib][lane] = g_csr[start + base + lane];
        __syncwarp();

        int j = 0;
        for (; j + 4 <= lim; j += 4) {
            uint64_t e0 = ebuf[wib][j + 0];
            uint64_t e1 = ebuf[wib][j + 1];
            uint64_t e2 = ebuf[wib][j + 2];
            uint64_t e3 = ebuf[wib][j + 3];
            float4 h0 = h4[(size_t)(uint32_t)e0 * 32 + lane];
            float4 h1 = h4[(size_t)(uint32_t)e1 * 32 + lane];
            float4 h2 = h4[(size_t)(uint32_t)e2 * 32 + lane];
            float4 h3 = h4[(size_t)(uint32_t)e3 * 32 + lane];
            float v0 = __uint_as_float((uint32_t)(e0 >> 32));
            float v1 = __uint_as_float((uint32_t)(e1 >> 32));
            float v2 = __uint_as_float((uint32_t)(e2 >> 32));
            float v3 = __uint_as_float((uint32_t)(e3 >> 32));
            acc0.x = fmaf(v0, h0.x, acc0.x); acc0.y = fmaf(v0, h0.y, acc0.y);
            acc0.z = fmaf(v0, h0.z, acc0.z); acc0.w = fmaf(v0, h0.w, acc0.w);
            acc1.x = fmaf(v1, h1.x, acc1.x); acc1.y = fmaf(v1, h1.y, acc1.y);
            acc1.z = fmaf(v1, h1.z, acc1.z); acc1.w = fmaf(v1, h1.w, acc1.w);
            acc0.x = fmaf(v2, h2.x, acc0.x); acc0.y = fmaf(v2, h2.y, acc0.y);
            acc0.z = fmaf(v2, h2.z, acc0.z); acc0.w = fmaf(v2, h2.w, acc0.w);
            acc1.x = fmaf(v3, h3.x, acc1.x); acc1.y = fmaf(v3, h3.y, acc1.y);
            acc1.z = fmaf(v3, h3.z, acc1.z); acc1.w = fmaf(v3, h3.w, acc1.w);
        }
        for (; j < lim; j++) {
            uint64_t e = ebuf[wib][j];
            float4 hv = h4[(size_t)(uint32_t)e * 32 + lane];
            float  v  = __uint_as_float((uint32_t)(e >> 32));
            acc0.x = fmaf(v, hv.x, acc0.x); acc0.y = fmaf(v, hv.y, acc0.y);
            acc0.z = fmaf(v, hv.z, acc0.z); acc0.w = fmaf(v, hv.w, acc0.w);
        }
    }

    float4 r;
    r.x = fmaxf(acc0.x + acc1.x, 0.f);
    r.y = fmaxf(acc0.y + acc1.y, 0.f);
    r.z = fmaxf(acc0.z + acc1.z, 0.f);
    r.w = fmaxf(acc0.w + acc1.w, 0.f);
    *(float4*)(out + (size_t)warp * N_DIM + lane * 4) = r;
}

extern "C" void kernel_launch(void* const* d_in, const int* in_sizes, int n_in,
                              void* d_out, int out_size) {
    const float* x    = (const float*)d_in[0];
    const float* W    = (const float*)d_in[1];
    const int*   rows = (const int*)d_in[2];
    const int*   cols = (const int*)d_in[3];
    const float* vals = (const float*)d_in[4];
    float* out = (float*)d_out;

    cudaFuncSetAttribute(gemm_mma_kernel,
                         cudaFuncAttributeMaxDynamicSharedMemorySize, SMEM_TOTAL);

    // CSR build
    zero_kernel<<<SCAN_BLK, 256>>>();
    count_kernel<<<(N_EDGES + 255) / 256, 256>>>(rows);
    scan_fused_kernel<<<SCAN_BLK, 256>>>();
    fill_kernel<<<(N_EDGES + 255) / 256, 256>>>(rows, cols, vals);

    // Dense projection h = x @ W
    wconv_kernel<<<(N_DIM * K_DIM) / 256, 256>>>(W);
    gemm_mma_kernel<<<(M_NODES + 127) / 128, 256, SMEM_TOTAL>>>(x);

    // Aggregate + relu, single write per row
    gather_kernel<<<(M_NODES * 32 + 255) / 256, 256>>>(out);
}